// round 10
// baseline (speedup 1.0000x reference)
#include <cuda_runtime.h>
#include <cuda_bf16.h>
#include <cstdint>

#define DMODEL  4096
#define NEXP    64
#define TPB     64                  // tokens per CTA
#define KC      16                  // K per smem tile
#define NIT     (DMODEL / KC)       // 256 tiles
#define THREADS 256

// smem byte offsets (per stage: XH 5120, XL 5120, WH 4608, WL 4608 = 19456)
#define ST_STRIDE 19456
#define OFF_XH    0
#define OFF_XL    5120
#define OFF_WH    10240
#define OFF_WL    14848
#define OFF_BIAS  (2 * ST_STRIDE)          // 38912
#define SM_BYTES  (OFF_BIAS + 256)

__device__ __forceinline__ uint32_t tf32_hi(float v) {
    uint32_t h;
    asm("cvt.rna.tf32.f32 %0, %1;" : "=r"(h) : "f"(v));
    return h;
}
__device__ __forceinline__ void mma_tf32(float* c, const uint32_t* a, uint32_t b0, uint32_t b1) {
    asm volatile("mma.sync.aligned.m16n8k8.row.col.f32.tf32.tf32.f32 "
                 "{%0,%1,%2,%3}, {%4,%5,%6,%7}, {%8,%9}, {%0,%1,%2,%3};"
                 : "+f"(c[0]), "+f"(c[1]), "+f"(c[2]), "+f"(c[3])
                 : "r"(a[0]), "r"(a[1]), "r"(a[2]), "r"(a[3]), "r"(b0), "r"(b1));
}

__global__ __launch_bounds__(THREADS, 2) void router_kernel(
    const float* __restrict__ x, const float* __restrict__ W,
    const float* __restrict__ b,
    float* __restrict__ probs_out, float* __restrict__ tkp_out,
    float* __restrict__ tki_out)
{
    __shared__ __align__(16) char sAll[SM_BYTES];

    const int tid  = threadIdx.x;
    const int wid  = tid >> 5;
    const int lane = tid & 31;
    const int rstripe = (wid & 3) * 16;     // token rows of this warp
    const int ncolbase = (wid >> 2) * 32;   // expert column half
    const int tok0 = blockIdx.x * TPB;

    if (tid < NEXP) *(float*)(sAll + OFF_BIAS + tid * 4) = b[tid];

    const int xt  = tid >> 2;               // token 0..63
    const int xc4 = (tid & 3) * 4;          // k offset 0,4,8,12
    const int wk  = tid >> 4;               // k row 0..15
    const int we4 = (tid & 15) * 4;         // expert col 0,4,..,60

    float acc[4][4];
    #pragma unroll
    for (int nb = 0; nb < 4; nb++)
        #pragma unroll
        for (int j = 0; j < 4; j++) acc[nb][j] = 0.f;

    float4 xr, wr;

    auto stage = [&](int st) {
        char* base = sAll + st * ST_STRIDE;
        {
            float v[4] = {xr.x, xr.y, xr.z, xr.w};
            uint32_t h[4], l[4];
            #pragma unroll
            for (int i = 0; i < 4; i++) {
                h[i] = tf32_hi(v[i]);
                l[i] = tf32_hi(v[i] - __uint_as_float(h[i]));
            }
            *(uint4*)(base + OFF_XH + (xt * 20 + xc4) * 4) = make_uint4(h[0], h[1], h[2], h[3]);
            *(uint4*)(base + OFF_XL + (xt * 20 + xc4) * 4) = make_uint4(l[0], l[1], l[2], l[3]);
        }
        {
            float v[4] = {wr.x, wr.y, wr.z, wr.w};
            uint32_t h[4], l[4];
            #pragma unroll
            for (int i = 0; i < 4; i++) {
                h[i] = tf32_hi(v[i]);
                l[i] = tf32_hi(v[i] - __uint_as_float(h[i]));
            }
            *(uint4*)(base + OFF_WH + (wk * 72 + we4) * 4) = make_uint4(h[0], h[1], h[2], h[3]);
            *(uint4*)(base + OFF_WL + (wk * 72 + we4) * 4) = make_uint4(l[0], l[1], l[2], l[3]);
        }
    };

    // ---- prologue ----
    xr = *(const float4*)&x[(size_t)(tok0 + xt) * DMODEL + xc4];
    wr = *(const float4*)&W[(size_t)wk * NEXP + we4];
    stage(0);

    const int tig = lane & 3;
    const int grp = lane >> 2;

    // ---- mainloop ----
    #pragma unroll 1
    for (int it = 0; it < NIT; it++) {
        const int s = it & 1;
        __syncthreads();

        if (it + 1 < NIT) {
            const int k0 = (it + 1) * KC;
            xr = *(const float4*)&x[(size_t)(tok0 + xt) * DMODEL + k0 + xc4];
            wr = *(const float4*)&W[(size_t)(k0 + wk) * NEXP + we4];
        }

        const float* Xh = (const float*)(sAll + s * ST_STRIDE + OFF_XH);
        const float* Xl = (const float*)(sAll + s * ST_STRIDE + OFF_XL);
        const float* Wh = (const float*)(sAll + s * ST_STRIDE + OFF_WH);
        const float* Wl = (const float*)(sAll + s * ST_STRIDE + OFF_WL);

        #pragma unroll
        for (int ks = 0; ks < 2; ks++) {
            const int ar = rstripe + grp;
            const int kk = ks * 8 + tig;
            uint32_t ah[4], al[4];
            ah[0] = __float_as_uint(Xh[ar * 20 + kk]);
            ah[1] = __float_as_uint(Xh[(ar + 8) * 20 + kk]);
            ah[2] = __float_as_uint(Xh[ar * 20 + kk + 4]);
            ah[3] = __float_as_uint(Xh[(ar + 8) * 20 + kk + 4]);
            al[0] = __float_as_uint(Xl[ar * 20 + kk]);
            al[1] = __float_as_uint(Xl[(ar + 8) * 20 + kk]);
            al[2] = __float_as_uint(Xl[ar * 20 + kk + 4]);
            al[3] = __float_as_uint(Xl[(ar + 8) * 20 + kk + 4]);
            #pragma unroll
            for (int nb = 0; nb < 4; nb++) {
                const int nc = ncolbase + nb * 8 + grp;
                uint32_t bh0 = __float_as_uint(Wh[kk * 72 + nc]);
                uint32_t bh1 = __float_as_uint(Wh[(kk + 4) * 72 + nc]);
                uint32_t bl0 = __float_as_uint(Wl[kk * 72 + nc]);
                uint32_t bl1 = __float_as_uint(Wl[(kk + 4) * 72 + nc]);
                mma_tf32(acc[nb], ah, bh0, bh1);
                mma_tf32(acc[nb], al, bh0, bh1);
                mma_tf32(acc[nb], ah, bl0, bl1);
            }
        }

        if (it + 1 < NIT) stage(s ^ 1);
    }

    // ---- epilogue: dump logits (stride 65), softmax + top-k with exact re-rank ----
    __syncthreads();
    {
        float* sf = (float*)sAll;
        const int ra = rstripe + grp;
        #pragma unroll
        for (int nb = 0; nb < 4; nb++) {
            const int cb = ncolbase + nb * 8 + tig * 2;
            sf[ra * 65 + cb]           = acc[nb][0];
            sf[ra * 65 + cb + 1]       = acc[nb][1];
            sf[(ra + 8) * 65 + cb]     = acc[nb][2];
            sf[(ra + 8) * 65 + cb + 1] = acc[nb][3];
        }
    }
    __syncthreads();

    if (tid < TPB) {
        const float* sf = (const float*)sAll;
        const float* sbias = (const float*)(sAll + OFF_BIAS);
        float p[64];
        #pragma unroll
        for (int c = 0; c < 64; c++)
            p[c] = sf[tid * 65 + c] + sbias[c];

        float m = p[0];
        #pragma unroll
        for (int c = 1; c < 64; c++) m = fmaxf(m, p[c]);
        float sum = 0.f;
        #pragma unroll
        for (int c = 0; c < 64; c++) { p[c] = __expf(p[c] - m); sum += p[c]; }
        const float inv = 1.f / sum;
        #pragma unroll
        for (int c = 0; c < 64; c++) p[c] *= inv;

        #pragma unroll
        for (int c4 = 0; c4 < 16; c4++)
            *(float4*)&probs_out[(size_t)(tok0 + tid) * NEXP + c4 * 4] =
                make_float4(p[c4 * 4], p[c4 * 4 + 1], p[c4 * 4 + 2], p[c4 * 4 + 3]);

        // ---- top-4 scan ----
        float t1 = -1.f, t2 = -1.f, t3 = -1.f, t4 = -1.f;
        int   i1 = 0,    i2 = 0,    i3 = 0,    i4 = 0;
        #pragma unroll
        for (int c = 0; c < 64; c++) {
            float pv = p[c];
            if (pv > t1)      { t4=t3; i4=i3; t3=t2; i3=i2; t2=t1; i2=i1; t1=pv; i1=c; }
            else if (pv > t2) { t4=t3; i4=i3; t3=t2; i3=i2; t2=pv; i2=c; }
            else if (pv > t3) { t4=t3; i4=i3; t3=pv; i3=c; }
            else if (pv > t4) { t4=pv; i4=c; }
        }

        // outputs (may be overridden by exact re-rank)
        float P1 = t1, P2 = t2;
        int   E1 = i1, E2 = i2;

        // ambiguity: top-1/2 order or top-2/3 membership within 250x error margin
        const float TAU = 5e-3f;
        bool amb = (t1 - t2 < TAU * t1) || (t2 - t3 < TAU * t2);

        unsigned fl = __ballot_sync(0xffffffffu, amb);
        while (fl) {
            const int src = __ffs(fl) - 1;
            fl &= fl - 1;
            const int stok = tok0 + (wid << 5) + src;
            int ci[4];
            ci[0] = __shfl_sync(0xffffffffu, i1, src);
            ci[1] = __shfl_sync(0xffffffffu, i2, src);
            ci[2] = __shfl_sync(0xffffffffu, i3, src);
            ci[3] = __shfl_sync(0xffffffffu, i4, src);

            // exact fp64 dot products, warp-parallel
            const float* xrow = x + (size_t)stok * DMODEL;
            double d0 = 0.0, d1 = 0.0, d2 = 0.0, d3 = 0.0;
            for (int j = lane; j < DMODEL; j += 32) {
                double xv = (double)xrow[j];
                const float* wrow = W + (size_t)j * NEXP;
                d0 += xv * (double)wrow[ci[0]];
                d1 += xv * (double)wrow[ci[1]];
                d2 += xv * (double)wrow[ci[2]];
                d3 += xv * (double)wrow[ci[3]];
            }
            #pragma unroll
            for (int o = 16; o; o >>= 1) {
                d0 += __shfl_xor_sync(0xffffffffu, d0, o);
                d1 += __shfl_xor_sync(0xffffffffu, d1, o);
                d2 += __shfl_xor_sync(0xffffffffu, d2, o);
                d3 += __shfl_xor_sync(0xffffffffu, d3, o);
            }

            if (lane == src) {
                double cd[4] = {d0 + (double)b[ci[0]], d1 + (double)b[ci[1]],
                                d2 + (double)b[ci[2]], d3 + (double)b[ci[3]]};
                // insertion sort desc, lower-index wins ties (lax.top_k semantics)
                #pragma unroll
                for (int a = 1; a < 4; a++)
                    #pragma unroll
                    for (int q = a; q > 0; q--) {
                        bool better = (cd[q] > cd[q-1]) ||
                                      (cd[q] == cd[q-1] && ci[q] < ci[q-1]);
                        if (better) {
                            double td = cd[q]; cd[q] = cd[q-1]; cd[q-1] = td;
                            int    ti = ci[q]; ci[q] = ci[q-1]; ci[q-1] = ti;
                        }
                    }
                E1 = ci[0]; E2 = ci[1];
                // prob values from the (accurate, already-validated) softmax
                P1 = __expf(sf[tid * 65 + E1] + sbias[E1] - m) * inv;
                P2 = __expf(sf[tid * 65 + E2] + sbias[E2] - m) * inv;
            }
        }

        const int token = tok0 + tid;
        const float is2 = 1.f / (P1 + P2 + 1e-9f);
        *(float2*)&tkp_out[(size_t)token * 2] = make_float2(P1 * is2, P2 * is2);
        *(float2*)&tki_out[(size_t)token * 2] = make_float2((float)E1, (float)E2);
    }
}

extern "C" void kernel_launch(void* const* d_in, const int* in_sizes, int n_in,
                              void* d_out, int out_size) {
    const float* x = (const float*)d_in[0];   // [4,4096,4096]
    const float* W = (const float*)d_in[1];   // [4096,64]
    const float* b = (const float*)d_in[2];   // [64]

    const int n_tokens = in_sizes[0] / DMODEL;        // 16384
    float* probs = (float*)d_out;
    float* tkp   = probs + (size_t)n_tokens * NEXP;
    float* tki   = tkp + (size_t)n_tokens * 2;

    router_kernel<<<n_tokens / TPB, THREADS>>>(x, W, b, probs, tkp, tki);
}

// round 11
// speedup vs baseline: 1.2299x; 1.2299x over previous
#include <cuda_runtime.h>
#include <cuda_bf16.h>
#include <cstdint>

#define DMODEL  4096
#define NEXP    64
#define TPB     128                 // tokens per CTA
#define KC      32                  // K per tile
#define NIT     (DMODEL / KC)       // 128 tiles
#define THREADS 256

// smem per stage: XH 8KB, XL 8KB, BH 4KB, BL 4KB = 24KB; 2 stages = 48KB
#define ST      24576
#define OFF_XH  0
#define OFF_XL  8192
#define OFF_BH  16384
#define OFF_BL  20480
#define SM_BYTES 49152

// Pre-split W fragment images per K-tile: 64 experts x 32 k bf16, SW128,
// 2 experts per 128B row (row = e&31, half = (e>>5)*64B). 4KB per tile per part.
__device__ uint4 g_whi[NIT * 256];
__device__ uint4 g_wlo[NIT * 256];

__device__ __forceinline__ uint32_t swz(uint32_t off) { return off ^ ((off >> 3) & 0x70); }

__device__ __forceinline__ uint32_t smem_u32(const void* p) {
    uint32_t a;
    asm("{ .reg .u64 t; cvta.to.shared.u64 t, %1; cvt.u32.u64 %0, t; }" : "=r"(a) : "l"(p));
    return a;
}
__device__ __forceinline__ void ldsm4(uint32_t* r, uint32_t addr) {
    asm volatile("ldmatrix.sync.aligned.m8n8.x4.shared.b16 {%0,%1,%2,%3}, [%4];"
                 : "=r"(r[0]), "=r"(r[1]), "=r"(r[2]), "=r"(r[3]) : "r"(addr));
}
__device__ __forceinline__ void mma_bf16(float* c, const uint32_t* a, const uint32_t* b) {
    asm volatile("mma.sync.aligned.m16n8k16.row.col.f32.bf16.bf16.f32 "
                 "{%0,%1,%2,%3}, {%4,%5,%6,%7}, {%8,%9}, {%0,%1,%2,%3};"
                 : "+f"(c[0]), "+f"(c[1]), "+f"(c[2]), "+f"(c[3])
                 : "r"(a[0]), "r"(a[1]), "r"(a[2]), "r"(a[3]), "r"(b[0]), "r"(b[1]));
}
__device__ __forceinline__ void cp16(uint32_t dst, const void* src) {
    asm volatile("cp.async.cg.shared.global [%0], [%1], 16;" :: "r"(dst), "l"(src));
}
__device__ __forceinline__ void cp_commit() { asm volatile("cp.async.commit_group;" ::: "memory"); }
__device__ __forceinline__ void cp_wait0()  { asm volatile("cp.async.wait_group 0;" ::: "memory"); }

// ---- W pre-split: fp32 -> (hi,lo) bf16, SW128 ldmatrix frag images (runs once/launch) ----
__global__ void convert_w_kernel(const float* __restrict__ W) {
    int t  = blockIdx.x * blockDim.x + threadIdx.x;   // 0 .. NIT*2048-1
    int kt = t >> 11;
    int r  = t & 2047;
    int kk = r >> 6;            // k within tile 0..31
    int e  = r & 63;            // expert
    float w = W[(size_t)(kt * KC + kk) * NEXP + e];
    __nv_bfloat16 hi = __float2bfloat16(w);
    __nv_bfloat16 lo = __float2bfloat16(w - __bfloat162float(hi));
    uint32_t off = (uint32_t)(e & 31) * 128u + (uint32_t)((e >> 5) << 6) + (uint32_t)kk * 2u;
    uint32_t sw  = swz(off);
    ((__nv_bfloat16*)g_whi)[kt * 2048 + (sw >> 1)] = hi;
    ((__nv_bfloat16*)g_wlo)[kt * 2048 + (sw >> 1)] = lo;
}

// ---- fused kernel: bf16 3-pass mma GEMM + softmax + top-2 with exact re-rank ----
__global__ __launch_bounds__(THREADS, 1) void router_kernel(
    const float* __restrict__ x, const float* __restrict__ W,
    const float* __restrict__ b,
    float* __restrict__ probs_out, float* __restrict__ tkp_out,
    float* __restrict__ tki_out)
{
    __shared__ __align__(1024) char sAll[SM_BYTES];
    const uint32_t sb = smem_u32(sAll);

    const int tid  = threadIdx.x;
    const int wid  = tid >> 5;
    const int lane = tid & 31;
    const int rstripe = (wid & 3) * 32;      // 32 token rows per warp (2 m16 tiles)
    const int nhalf   = wid >> 2;            // 32 experts per warp (4 n8 tiles)
    const int tok0 = blockIdx.x * TPB;

    // X load map: 4 float4 per thread per tile (128 tok x 8 float4-chunks)
    int xt[4], xc4[4];
    #pragma unroll
    for (int r = 0; r < 4; r++) {
        int v = tid + r * THREADS;           // 0..1023
        xt[r]  = v >> 3;                     // token 0..127
        xc4[r] = v & 7;                      // k-chunk (k = xc4*4)
    }

    float acc0[4][4], acc1[4][4];
    #pragma unroll
    for (int nb = 0; nb < 4; nb++)
        #pragma unroll
        for (int j = 0; j < 4; j++) { acc0[nb][j] = 0.f; acc1[nb][j] = 0.f; }

    float4 xr[4];

    auto stage_x = [&](int st) {
        #pragma unroll
        for (int r = 0; r < 4; r++) {
            float4 f = xr[r];
            uint32_t h01, h23, l01, l23;
            asm("cvt.rn.satfinite.bf16x2.f32 %0, %1, %2;" : "=r"(h01) : "f"(f.y), "f"(f.x));
            asm("cvt.rn.satfinite.bf16x2.f32 %0, %1, %2;" : "=r"(h23) : "f"(f.w), "f"(f.z));
            float hx = __uint_as_float(h01 << 16);
            float hy = __uint_as_float(h01 & 0xffff0000u);
            float hz = __uint_as_float(h23 << 16);
            float hw = __uint_as_float(h23 & 0xffff0000u);
            float lx = f.x - hx, ly = f.y - hy, lz = f.z - hz, lw = f.w - hw;
            asm("cvt.rn.satfinite.bf16x2.f32 %0, %1, %2;" : "=r"(l01) : "f"(ly), "f"(lx));
            asm("cvt.rn.satfinite.bf16x2.f32 %0, %1, %2;" : "=r"(l23) : "f"(lw), "f"(lz));
            uint32_t off = (uint32_t)(xt[r] & 63) * 128u + (uint32_t)((xt[r] >> 6) << 6)
                         + (uint32_t)xc4[r] * 8u;
            uint32_t sw = swz(off);
            *(uint2*)(sAll + st * ST + OFF_XH + sw) = make_uint2(h01, h23);
            *(uint2*)(sAll + st * ST + OFF_XL + sw) = make_uint2(l01, l23);
        }
    };

    // ---- prologue: tile 0 ----
    #pragma unroll
    for (int r = 0; r < 4; r++)
        xr[r] = *(const float4*)&x[(size_t)(tok0 + xt[r]) * DMODEL + xc4[r] * 4];
    stage_x(0);
    cp16(sb + OFF_BH + tid * 16, (const char*)g_whi + tid * 16);
    cp16(sb + OFF_BL + tid * 16, (const char*)g_wlo + tid * 16);
    cp_commit();

    // ldmatrix lane geometry
    const int at0 = rstripe + (lane & 15);
    const int at1 = at0 + 16;
    const uint32_t ab0 = (uint32_t)(at0 & 63) * 128u + (uint32_t)((at0 >> 6) << 6);
    const uint32_t ab1 = (uint32_t)(at1 & 63) * 128u + (uint32_t)((at1 >> 6) << 6);
    const uint32_t akhi = (uint32_t)((lane >> 4) << 4);
    uint32_t bb[2];
    #pragma unroll
    for (int q = 0; q < 2; q++) {
        int be = nhalf * 32 + q * 16 + (lane & 7) + ((lane & 16) >> 1);
        bb[q] = (uint32_t)(be & 31) * 128u + (uint32_t)((be >> 5) << 6);
    }
    const uint32_t bkhi = (uint32_t)((lane & 8) << 1);

    // ---- mainloop ----
    #pragma unroll 1
    for (int it = 0; it < NIT; it++) {
        const int s = it & 1;

        if (it + 1 < NIT) {             // issue next-tile x LDGs early
            const int k0 = (it + 1) * KC;
            #pragma unroll
            for (int r = 0; r < 4; r++)
                xr[r] = *(const float4*)&x[(size_t)(tok0 + xt[r]) * DMODEL + k0 + xc4[r] * 4];
        }

        cp_wait0();
        __syncthreads();                // stage s (X STS + B cp.async) visible

        if (it + 1 < NIT) {             // B for next stage: pure async copy
            const int d = s ^ 1;
            cp16(sb + d * ST + OFF_BH + tid * 16, (const char*)g_whi + (it + 1) * 4096 + tid * 16);
            cp16(sb + d * ST + OFF_BL + tid * 16, (const char*)g_wlo + (it + 1) * 4096 + tid * 16);
            cp_commit();
        }

        const uint32_t aXH = sb + s * ST + OFF_XH;
        const uint32_t aXL = sb + s * ST + OFF_XL;
        const uint32_t aBH = sb + s * ST + OFF_BH;
        const uint32_t aBL = sb + s * ST + OFF_BL;

        #pragma unroll
        for (int ks = 0; ks < 2; ks++) {
            uint32_t ah0[4], al0[4], ah1[4], al1[4], bh[8], bl[8];
            const uint32_t ao0 = swz(ab0 + (uint32_t)ks * 32u + akhi);
            const uint32_t ao1 = swz(ab1 + (uint32_t)ks * 32u + akhi);
            ldsm4(ah0, aXH + ao0);
            ldsm4(al0, aXL + ao0);
            ldsm4(ah1, aXH + ao1);
            ldsm4(al1, aXL + ao1);
            #pragma unroll
            for (int q = 0; q < 2; q++) {
                const uint32_t bo = swz(bb[q] + (uint32_t)ks * 32u + bkhi);
                ldsm4(bh + q * 4, aBH + bo);
                ldsm4(bl + q * 4, aBL + bo);
            }
            #pragma unroll
            for (int nb = 0; nb < 4; nb++) {
                mma_bf16(acc0[nb], ah0, bh + nb * 2);
                mma_bf16(acc0[nb], al0, bh + nb * 2);
                mma_bf16(acc0[nb], ah0, bl + nb * 2);
                mma_bf16(acc1[nb], ah1, bh + nb * 2);
                mma_bf16(acc1[nb], al1, bh + nb * 2);
                mma_bf16(acc1[nb], ah1, bl + nb * 2);
            }
        }

        if (it + 1 < NIT) stage_x(s ^ 1);
    }

    // ---- epilogue: logits -> smem (stride 65), softmax + top-k + exact re-rank ----
    __syncthreads();
    {
        float* sf = (float*)sAll;
        const int grp = lane >> 2, tig = lane & 3;
        const int ra0 = rstripe + grp;
        const int ra1 = rstripe + 16 + grp;
        #pragma unroll
        for (int nb = 0; nb < 4; nb++) {
            const int cb = nhalf * 32 + nb * 8 + tig * 2;
            sf[ra0 * 65 + cb]            = acc0[nb][0];
            sf[ra0 * 65 + cb + 1]        = acc0[nb][1];
            sf[(ra0 + 8) * 65 + cb]      = acc0[nb][2];
            sf[(ra0 + 8) * 65 + cb + 1]  = acc0[nb][3];
            sf[ra1 * 65 + cb]            = acc1[nb][0];
            sf[ra1 * 65 + cb + 1]        = acc1[nb][1];
            sf[(ra1 + 8) * 65 + cb]      = acc1[nb][2];
            sf[(ra1 + 8) * 65 + cb + 1]  = acc1[nb][3];
        }
    }
    __syncthreads();

    if (tid < TPB) {
        const float* sf = (const float*)sAll;
        float p[64];
        #pragma unroll
        for (int c = 0; c < 64; c++)
            p[c] = sf[tid * 65 + c] + __ldg(&b[c]);

        float m = p[0];
        #pragma unroll
        for (int c = 1; c < 64; c++) m = fmaxf(m, p[c]);
        float sum = 0.f;
        #pragma unroll
        for (int c = 0; c < 64; c++) { p[c] = __expf(p[c] - m); sum += p[c]; }
        const float inv = 1.f / sum;
        #pragma unroll
        for (int c = 0; c < 64; c++) p[c] *= inv;

        #pragma unroll
        for (int c4 = 0; c4 < 16; c4++)
            *(float4*)&probs_out[(size_t)(tok0 + tid) * NEXP + c4 * 4] =
                make_float4(p[c4 * 4], p[c4 * 4 + 1], p[c4 * 4 + 2], p[c4 * 4 + 3]);

        // top-4 scan
        float t1 = -1.f, t2 = -1.f, t3 = -1.f, t4 = -1.f;
        int   i1 = 0,    i2 = 0,    i3 = 0,    i4 = 0;
        #pragma unroll
        for (int c = 0; c < 64; c++) {
            float pv = p[c];
            if (pv > t1)      { t4=t3; i4=i3; t3=t2; i3=i2; t2=t1; i2=i1; t1=pv; i1=c; }
            else if (pv > t2) { t4=t3; i4=i3; t3=t2; i3=i2; t2=pv; i2=c; }
            else if (pv > t3) { t4=t3; i4=i3; t3=pv; i3=c; }
            else if (pv > t4) { t4=pv; i4=c; }
        }

        float P1 = t1, P2 = t2;
        int   E1 = i1, E2 = i2;

        const float TAU = 5e-3f;
        bool amb = (t1 - t2 < TAU * t1) || (t2 - t3 < TAU * t2);

        unsigned fl = __ballot_sync(0xffffffffu, amb);
        while (fl) {
            const int src = __ffs(fl) - 1;
            fl &= fl - 1;
            const int stok = tok0 + ((tid >> 5) << 5) + src;
            int ci[4];
            ci[0] = __shfl_sync(0xffffffffu, i1, src);
            ci[1] = __shfl_sync(0xffffffffu, i2, src);
            ci[2] = __shfl_sync(0xffffffffu, i3, src);
            ci[3] = __shfl_sync(0xffffffffu, i4, src);

            const float* xrow = x + (size_t)stok * DMODEL;
            double d0 = 0.0, d1 = 0.0, d2 = 0.0, d3 = 0.0;
            for (int j = lane; j < DMODEL; j += 32) {
                double xv = (double)xrow[j];
                const float* wrow = W + (size_t)j * NEXP;
                d0 += xv * (double)wrow[ci[0]];
                d1 += xv * (double)wrow[ci[1]];
                d2 += xv * (double)wrow[ci[2]];
                d3 += xv * (double)wrow[ci[3]];
            }
            #pragma unroll
            for (int o = 16; o; o >>= 1) {
                d0 += __shfl_xor_sync(0xffffffffu, d0, o);
                d1 += __shfl_xor_sync(0xffffffffu, d1, o);
                d2 += __shfl_xor_sync(0xffffffffu, d2, o);
                d3 += __shfl_xor_sync(0xffffffffu, d3, o);
            }

            if (lane == src) {
                double cd[4] = {d0 + (double)b[ci[0]], d1 + (double)b[ci[1]],
                                d2 + (double)b[ci[2]], d3 + (double)b[ci[3]]};
                #pragma unroll
                for (int a = 1; a < 4; a++)
                    #pragma unroll
                    for (int q = a; q > 0; q--) {
                        bool better = (cd[q] > cd[q-1]) ||
                                      (cd[q] == cd[q-1] && ci[q] < ci[q-1]);
                        if (better) {
                            double td = cd[q]; cd[q] = cd[q-1]; cd[q-1] = td;
                            int    ti = ci[q]; ci[q] = ci[q-1]; ci[q-1] = ti;
                        }
                    }
                E1 = ci[0]; E2 = ci[1];
                P1 = __expf(sf[tid * 65 + E1] + __ldg(&b[E1]) - m) * inv;
                P2 = __expf(sf[tid * 65 + E2] + __ldg(&b[E2]) - m) * inv;
            }
        }

        const int token = tok0 + tid;
        const float is2 = 1.f / (P1 + P2 + 1e-9f);
        *(float2*)&tkp_out[(size_t)token * 2] = make_float2(P1 * is2, P2 * is2);
        *(float2*)&tki_out[(size_t)token * 2] = make_float2((float)E1, (float)E2);
    }
}

extern "C" void kernel_launch(void* const* d_in, const int* in_sizes, int n_in,
                              void* d_out, int out_size) {
    const float* x = (const float*)d_in[0];   // [4,4096,4096]
    const float* W = (const float*)d_in[1];   // [4096,64]
    const float* b = (const float*)d_in[2];   // [64]

    const int n_tokens = in_sizes[0] / DMODEL;        // 16384
    float* probs = (float*)d_out;
    float* tkp   = probs + (size_t)n_tokens * NEXP;
    float* tki   = tkp + (size_t)n_tokens * 2;

    convert_w_kernel<<<(NIT * 2048) / 256, 256>>>(W);
    router_kernel<<<n_tokens / TPB, THREADS>>>(x, W, b, probs, tkp, tki);
}

// round 12
// speedup vs baseline: 1.2432x; 1.0108x over previous
#include <cuda_runtime.h>
#include <cuda_bf16.h>
#include <cstdint>

#define DMODEL  4096
#define NEXP    64
#define TPB     64                  // tokens per CTA
#define KC      32                  // K per tile
#define NSPLIT  4
#define KSPAN   (DMODEL / NSPLIT)   // 1024
#define NIT_S   (KSPAN / KC)        // 32 iterations per CTA
#define NTILES  (DMODEL / KC)       // 128 total k-tiles
#define THREADS 256
#define NTOK    16384

// smem per stage: XH 4KB, XL 4KB, BH 4KB, BL 4KB = 16KB; 2 stages = 32KB
#define ST      16384
#define OFF_XH  0
#define OFF_XL  4096
#define OFF_BH  8192
#define OFF_BL  12288
#define SM_BYTES 32768

// Pre-split W frag images per k-tile: 64 experts x 32 k bf16, SW128 packed
__device__ uint4 g_whi[NTILES * 256];
__device__ uint4 g_wlo[NTILES * 256];
// Split-K partial logits [split][token][expert]
__device__ float g_partial[NSPLIT][NTOK][NEXP];

__device__ __forceinline__ uint32_t swz(uint32_t off) { return off ^ ((off >> 3) & 0x70); }
__device__ __forceinline__ uint32_t smem_u32(const void* p) {
    uint32_t a;
    asm("{ .reg .u64 t; cvta.to.shared.u64 t, %1; cvt.u32.u64 %0, t; }" : "=r"(a) : "l"(p));
    return a;
}
__device__ __forceinline__ void ldsm4(uint32_t* r, uint32_t addr) {
    asm volatile("ldmatrix.sync.aligned.m8n8.x4.shared.b16 {%0,%1,%2,%3}, [%4];"
                 : "=r"(r[0]), "=r"(r[1]), "=r"(r[2]), "=r"(r[3]) : "r"(addr));
}
__device__ __forceinline__ void mma_bf16(float* c, const uint32_t* a, const uint32_t* b) {
    asm volatile("mma.sync.aligned.m16n8k16.row.col.f32.bf16.bf16.f32 "
                 "{%0,%1,%2,%3}, {%4,%5,%6,%7}, {%8,%9}, {%0,%1,%2,%3};"
                 : "+f"(c[0]), "+f"(c[1]), "+f"(c[2]), "+f"(c[3])
                 : "r"(a[0]), "r"(a[1]), "r"(a[2]), "r"(a[3]), "r"(b[0]), "r"(b[1]));
}
__device__ __forceinline__ void cp16(uint32_t dst, const void* src) {
    asm volatile("cp.async.cg.shared.global [%0], [%1], 16;" :: "r"(dst), "l"(src));
}
__device__ __forceinline__ void cp_commit() { asm volatile("cp.async.commit_group;" ::: "memory"); }
__device__ __forceinline__ void cp_wait0()  { asm volatile("cp.async.wait_group 0;" ::: "memory"); }

// ---- W pre-split (once per launch) ----
__global__ void convert_w_kernel(const float* __restrict__ W) {
    int t  = blockIdx.x * blockDim.x + threadIdx.x;
    int kt = t >> 11;
    int r  = t & 2047;
    int kk = r >> 6;
    int e  = r & 63;
    float w = W[(size_t)(kt * KC + kk) * NEXP + e];
    __nv_bfloat16 hi = __float2bfloat16(w);
    __nv_bfloat16 lo = __float2bfloat16(w - __bfloat162float(hi));
    uint32_t off = (uint32_t)(e & 31) * 128u + (uint32_t)((e >> 5) << 6) + (uint32_t)kk * 2u;
    uint32_t sw  = swz(off);
    ((__nv_bfloat16*)g_whi)[kt * 2048 + (sw >> 1)] = hi;
    ((__nv_bfloat16*)g_wlo)[kt * 2048 + (sw >> 1)] = lo;
}

// ---- split-K GEMM: partial logits for 64 tokens x 64 experts x 1024 K ----
__global__ __launch_bounds__(THREADS, 3) void gemm_kernel(const float* __restrict__ x)
{
    __shared__ __align__(1024) char sAll[SM_BYTES];
    const uint32_t sb = smem_u32(sAll);

    const int tid  = threadIdx.x;
    const int wid  = tid >> 5;
    const int lane = tid & 31;
    const int rstripe = (wid & 3) * 16;      // 16 token rows per warp
    const int nhalf   = wid >> 2;            // 32 experts per warp
    const int tok0   = blockIdx.x * TPB;
    const int ksplit = blockIdx.y;
    const int kbase  = ksplit * KSPAN;

    // X load map: 2 float4/thread (64 tok x 8 chunks = 512 float4)
    const int xt0 = tid >> 3,           xc0 = tid & 7;
    const int xt1 = (tid + 256) >> 3,   xc1 = tid & 7;   // (tid+256)&7 == tid&7

    float acc[4][4];
    #pragma unroll
    for (int nb = 0; nb < 4; nb++)
        #pragma unroll
        for (int j = 0; j < 4; j++) acc[nb][j] = 0.f;

    float4 xr0, xr1;

    auto stage_x = [&](int st) {
        #pragma unroll
        for (int r = 0; r < 2; r++) {
            float4 f = r ? xr1 : xr0;
            int xt = r ? xt1 : xt0, xc = r ? xc1 : xc0;
            uint32_t h01, h23, l01, l23;
            asm("cvt.rn.satfinite.bf16x2.f32 %0, %1, %2;" : "=r"(h01) : "f"(f.y), "f"(f.x));
            asm("cvt.rn.satfinite.bf16x2.f32 %0, %1, %2;" : "=r"(h23) : "f"(f.w), "f"(f.z));
            float hx = __uint_as_float(h01 << 16);
            float hy = __uint_as_float(h01 & 0xffff0000u);
            float hz = __uint_as_float(h23 << 16);
            float hw = __uint_as_float(h23 & 0xffff0000u);
            float lx = f.x - hx, ly = f.y - hy, lz = f.z - hz, lw = f.w - hw;
            asm("cvt.rn.satfinite.bf16x2.f32 %0, %1, %2;" : "=r"(l01) : "f"(ly), "f"(lx));
            asm("cvt.rn.satfinite.bf16x2.f32 %0, %1, %2;" : "=r"(l23) : "f"(lw), "f"(lz));
            uint32_t off = (uint32_t)(xt & 31) * 128u + (uint32_t)((xt >> 5) << 6)
                         + (uint32_t)xc * 8u;
            uint32_t sw = swz(off);
            *(uint2*)(sAll + st * ST + OFF_XH + sw) = make_uint2(h01, h23);
            *(uint2*)(sAll + st * ST + OFF_XL + sw) = make_uint2(l01, l23);
        }
    };

    // ---- prologue ----
    xr0 = *(const float4*)&x[(size_t)(tok0 + xt0) * DMODEL + kbase + xc0 * 4];
    xr1 = *(const float4*)&x[(size_t)(tok0 + xt1) * DMODEL + kbase + xc1 * 4];
    stage_x(0);
    {
        const int kt = ksplit * NIT_S;
        cp16(sb + OFF_BH + tid * 16, (const char*)g_whi + kt * 4096 + tid * 16);
        cp16(sb + OFF_BL + tid * 16, (const char*)g_wlo + kt * 4096 + tid * 16);
        cp_commit();
    }

    // ldmatrix lane geometry (verified R7 layout)
    const int at = rstripe + (lane & 15);
    const uint32_t ab   = (uint32_t)(at & 31) * 128u + (uint32_t)((at >> 5) << 6);
    const uint32_t akhi = (uint32_t)((lane >> 4) << 4);
    uint32_t bb[2];
    #pragma unroll
    for (int q = 0; q < 2; q++) {
        int be = nhalf * 32 + q * 16 + (lane & 7) + ((lane & 16) >> 1);
        bb[q] = (uint32_t)(be & 31) * 128u + (uint32_t)((be >> 5) << 6);
    }
    const uint32_t bkhi = (uint32_t)((lane & 8) << 1);

    // ---- mainloop: 32 iterations ----
    #pragma unroll 1
    for (int it = 0; it < NIT_S; it++) {
        const int s = it & 1;

        if (it + 1 < NIT_S) {
            const int k0 = kbase + (it + 1) * KC;
            xr0 = *(const float4*)&x[(size_t)(tok0 + xt0) * DMODEL + k0 + xc0 * 4];
            xr1 = *(const float4*)&x[(size_t)(tok0 + xt1) * DMODEL + k0 + xc1 * 4];
        }

        cp_wait0();
        __syncthreads();

        if (it + 1 < NIT_S) {
            const int d = s ^ 1;
            const int kt = ksplit * NIT_S + it + 1;
            cp16(sb + d * ST + OFF_BH + tid * 16, (const char*)g_whi + kt * 4096 + tid * 16);
            cp16(sb + d * ST + OFF_BL + tid * 16, (const char*)g_wlo + kt * 4096 + tid * 16);
            cp_commit();
        }

        const uint32_t aXH = sb + s * ST + OFF_XH;
        const uint32_t aXL = sb + s * ST + OFF_XL;
        const uint32_t aBH = sb + s * ST + OFF_BH;
        const uint32_t aBL = sb + s * ST + OFF_BL;

        #pragma unroll
        for (int ks = 0; ks < 2; ks++) {
            uint32_t ah[4], al[4], bh[8], bl[8];
            const uint32_t ao = swz(ab + (uint32_t)ks * 32u + akhi);
            ldsm4(ah, aXH + ao);
            ldsm4(al, aXL + ao);
            #pragma unroll
            for (int q = 0; q < 2; q++) {
                const uint32_t bo = swz(bb[q] + (uint32_t)ks * 32u + bkhi);
                ldsm4(bh + q * 4, aBH + bo);
                ldsm4(bl + q * 4, aBL + bo);
            }
            #pragma unroll
            for (int nb = 0; nb < 4; nb++) {
                mma_bf16(acc[nb], ah, bh + nb * 2);
                mma_bf16(acc[nb], al, bh + nb * 2);
                mma_bf16(acc[nb], ah, bl + nb * 2);
            }
        }

        if (it + 1 < NIT_S) stage_x(s ^ 1);
    }

    // ---- write partial fragments ----
    {
        float* dst = &g_partial[ksplit][tok0][0];
        const int grp = lane >> 2, tig = lane & 3;
        const int ra = rstripe + grp;
        #pragma unroll
        for (int nb = 0; nb < 4; nb++) {
            const int cb = nhalf * 32 + nb * 8 + tig * 2;
            *(float2*)&dst[ra * NEXP + cb]       = make_float2(acc[nb][0], acc[nb][1]);
            *(float2*)&dst[(ra + 8) * NEXP + cb] = make_float2(acc[nb][2], acc[nb][3]);
        }
    }
}

// ---- reduce: sum splits + bias, softmax, top-2 with exact fp64 re-rank ----
__global__ __launch_bounds__(128, 8) void reduce_kernel(
    const float* __restrict__ x, const float* __restrict__ W,
    const float* __restrict__ b,
    float* __restrict__ probs_out, float* __restrict__ tkp_out,
    float* __restrict__ tki_out)
{
    __shared__ float sf[128 * 65];
    const int tid   = threadIdx.x;
    const int lane  = tid & 31;
    const int token = blockIdx.x * 128 + tid;

    float p[64];
    #pragma unroll
    for (int c4 = 0; c4 < 16; c4++) {
        float4 v = *(const float4*)&g_partial[0][token][c4 * 4];
        p[c4*4] = v.x; p[c4*4+1] = v.y; p[c4*4+2] = v.z; p[c4*4+3] = v.w;
    }
    #pragma unroll
    for (int s = 1; s < NSPLIT; s++)
        #pragma unroll
        for (int c4 = 0; c4 < 16; c4++) {
            float4 v = *(const float4*)&g_partial[s][token][c4 * 4];
            p[c4*4]   += v.x; p[c4*4+1] += v.y;
            p[c4*4+2] += v.z; p[c4*4+3] += v.w;
        }
    #pragma unroll
    for (int c = 0; c < 64; c++) {
        p[c] += __ldg(&b[c]);
        sf[tid * 65 + c] = p[c];             // keep logits for re-rank prob fetch
    }

    float m = p[0];
    #pragma unroll
    for (int c = 1; c < 64; c++) m = fmaxf(m, p[c]);
    float sum = 0.f;
    #pragma unroll
    for (int c = 0; c < 64; c++) { p[c] = __expf(p[c] - m); sum += p[c]; }
    const float inv = 1.f / sum;
    #pragma unroll
    for (int c = 0; c < 64; c++) p[c] *= inv;

    #pragma unroll
    for (int c4 = 0; c4 < 16; c4++)
        *(float4*)&probs_out[(size_t)token * NEXP + c4 * 4] =
            make_float4(p[c4*4], p[c4*4+1], p[c4*4+2], p[c4*4+3]);

    // top-4 scan
    float t1 = -1.f, t2 = -1.f, t3 = -1.f, t4 = -1.f;
    int   i1 = 0,    i2 = 0,    i3 = 0,    i4 = 0;
    #pragma unroll
    for (int c = 0; c < 64; c++) {
        float pv = p[c];
        if (pv > t1)      { t4=t3; i4=i3; t3=t2; i3=i2; t2=t1; i2=i1; t1=pv; i1=c; }
        else if (pv > t2) { t4=t3; i4=i3; t3=t2; i3=i2; t2=pv; i2=c; }
        else if (pv > t3) { t4=t3; i4=i3; t3=pv; i3=c; }
        else if (pv > t4) { t4=pv; i4=c; }
    }

    float P1 = t1, P2 = t2;
    int   E1 = i1, E2 = i2;

    const float TAU = 5e-3f;
    bool amb = (t1 - t2 < TAU * t1) || (t2 - t3 < TAU * t2);

    unsigned fl = __ballot_sync(0xffffffffu, amb);
    while (fl) {
        const int src = __ffs(fl) - 1;
        fl &= fl - 1;
        const int stok = blockIdx.x * 128 + ((tid >> 5) << 5) + src;
        int ci[4];
        ci[0] = __shfl_sync(0xffffffffu, i1, src);
        ci[1] = __shfl_sync(0xffffffffu, i2, src);
        ci[2] = __shfl_sync(0xffffffffu, i3, src);
        ci[3] = __shfl_sync(0xffffffffu, i4, src);

        const float* xrow = x + (size_t)stok * DMODEL;
        double d0 = 0.0, d1 = 0.0, d2 = 0.0, d3 = 0.0;
        for (int j = lane; j < DMODEL; j += 32) {
            double xv = (double)xrow[j];
            const float* wrow = W + (size_t)j * NEXP;
            d0 += xv * (double)wrow[ci[0]];
            d1 += xv * (double)wrow[ci[1]];
            d2 += xv * (double)wrow[ci[2]];
            d3 += xv * (double)wrow[ci[3]];
        }
        #pragma unroll
        for (int o = 16; o; o >>= 1) {
            d0 += __shfl_xor_sync(0xffffffffu, d0, o);
            d1 += __shfl_xor_sync(0xffffffffu, d1, o);
            d2 += __shfl_xor_sync(0xffffffffu, d2, o);
            d3 += __shfl_xor_sync(0xffffffffu, d3, o);
        }

        if (lane == src) {
            double cd[4] = {d0 + (double)b[ci[0]], d1 + (double)b[ci[1]],
                            d2 + (double)b[ci[2]], d3 + (double)b[ci[3]]};
            #pragma unroll
            for (int a = 1; a < 4; a++)
                #pragma unroll
                for (int q = a; q > 0; q--) {
                    bool better = (cd[q] > cd[q-1]) ||
                                  (cd[q] == cd[q-1] && ci[q] < ci[q-1]);
                    if (better) {
                        double td = cd[q]; cd[q] = cd[q-1]; cd[q-1] = td;
                        int    ti = ci[q]; ci[q] = ci[q-1]; ci[q-1] = ti;
                    }
                }
            E1 = ci[0]; E2 = ci[1];
            P1 = __expf(sf[tid * 65 + E1] - m) * inv;
            P2 = __expf(sf[tid * 65 + E2] - m) * inv;
        }
    }

    const float is2 = 1.f / (P1 + P2 + 1e-9f);
    *(float2*)&tkp_out[(size_t)token * 2] = make_float2(P1 * is2, P2 * is2);
    *(float2*)&tki_out[(size_t)token * 2] = make_float2((float)E1, (float)E2);
}

extern "C" void kernel_launch(void* const* d_in, const int* in_sizes, int n_in,
                              void* d_out, int out_size) {
    const float* x = (const float*)d_in[0];   // [4,4096,4096]
    const float* W = (const float*)d_in[1];   // [4096,64]
    const float* b = (const float*)d_in[2];   // [64]

    const int n_tokens = in_sizes[0] / DMODEL;        // 16384
    float* probs = (float*)d_out;
    float* tkp   = probs + (size_t)n_tokens * NEXP;
    float* tki   = tkp + (size_t)n_tokens * 2;

    convert_w_kernel<<<(NTILES * 2048) / 256, 256>>>(W);
    dim3 g(n_tokens / TPB, NSPLIT);                   // 256 x 4 = 1024 CTAs
    gemm_kernel<<<g, THREADS>>>(x);
    reduce_kernel<<<n_tokens / 128, 128>>>(x, W, b, probs, tkp, tki);
}

// round 13
// speedup vs baseline: 2.3977x; 1.9286x over previous
#include <cuda_runtime.h>
#include <cuda_bf16.h>
#include <cstdint>

#define DMODEL  4096
#define NEXP    64
#define TPB     64                  // tokens per CTA
#define KC      32                  // K per tile
#define NIT     (DMODEL / KC)       // 128 tiles
#define THREADS 256

#define SXS 66                      // xs row stride in floats (2-way STS, LDS.64-aligned)
#define SWS 72                      // ws row stride in floats (2-way, LDS.128-aligned)

#define OFF_XS   0
#define XS_BYTES (2 * KC * SXS * 4)             // 16896
#define OFF_WS   XS_BYTES
#define WS_BYTES (2 * KC * SWS * 4)             // 18432
#define OFF_BIAS (OFF_XS + XS_BYTES + WS_BYTES) // 35328
#define SM_BYTES (OFF_BIAS + 256)

__device__ __forceinline__ uint32_t smem_u32(const void* p) {
    uint32_t a;
    asm("{ .reg .u64 t; cvta.to.shared.u64 t, %1; cvt.u32.u64 %0, t; }" : "=r"(a) : "l"(p));
    return a;
}
__device__ __forceinline__ void cp16(uint32_t dst, const void* src) {
    asm volatile("cp.async.cg.shared.global [%0], [%1], 16;" :: "r"(dst), "l"(src));
}
__device__ __forceinline__ void cp_commit() { asm volatile("cp.async.commit_group;" ::: "memory"); }
__device__ __forceinline__ void cp_wait0()  { asm volatile("cp.async.wait_group 0;" ::: "memory"); }

__global__ __launch_bounds__(THREADS, 2) void router_kernel(
    const float* __restrict__ x, const float* __restrict__ W,
    const float* __restrict__ b,
    float* __restrict__ probs_out, float* __restrict__ tkp_out,
    float* __restrict__ tki_out)
{
    __shared__ __align__(16) char sAll[SM_BYTES];
    const uint32_t sb = smem_u32(sAll);

    const int tid  = threadIdx.x;
    const int tx   = tid & 15;          // 4 experts: e0 = tx*4
    const int ty   = tid >> 4;          // 4 tokens:  t0 = ty*4
    const int e0   = tx * 4;
    const int t0   = ty * 4;
    const int tok0 = blockIdx.x * TPB;

    float* const xsBase = (float*)(sAll + OFF_XS);   // [2][KC][SXS]
    float* const wsBase = (float*)(sAll + OFF_WS);   // [2][KC][SWS]

    if (tid < NEXP) *(float*)(sAll + OFF_BIAS + tid * 4) = b[tid];

    // x load map: 2 float4/thread per tile (64 tok x 8 chunks)
    const int xt0 = tid >> 3;            const int xc0 = (tid & 7) * 4;
    const int xt1 = (tid + 256) >> 3;    const int xc1 = xc0;
    // W cp.async map: 2 float4/thread per tile (32 k x 16 chunks)
    const int wk0 = tid >> 4;            const int we0 = (tid & 15) * 4;
    const int wk1 = (tid + 256) >> 4;    const int we1 = we0;

    float acc[4][4];
    #pragma unroll
    for (int i = 0; i < 4; i++)
        #pragma unroll
        for (int j = 0; j < 4; j++) acc[i][j] = 0.f;

    float4 xr0, xr1;

    auto stage_x = [&](int st) {
        float* xs = xsBase + st * KC * SXS;
        float v0[4] = {xr0.x, xr0.y, xr0.z, xr0.w};
        float v1[4] = {xr1.x, xr1.y, xr1.z, xr1.w};
        #pragma unroll
        for (int i = 0; i < 4; i++) {
            xs[(xc0 + i) * SXS + xt0] = v0[i];
            xs[(xc1 + i) * SXS + xt1] = v1[i];
        }
    };

    // ---- prologue: tile 0 ----
    xr0 = *(const float4*)&x[(size_t)(tok0 + xt0) * DMODEL + xc0];
    xr1 = *(const float4*)&x[(size_t)(tok0 + xt1) * DMODEL + xc1];
    stage_x(0);
    cp16(sb + OFF_WS + (wk0 * SWS + we0) * 4, &W[(size_t)wk0 * NEXP + we0]);
    cp16(sb + OFF_WS + (wk1 * SWS + we1) * 4, &W[(size_t)wk1 * NEXP + we1]);
    cp_commit();

    // ---- mainloop ----
    #pragma unroll 1
    for (int it = 0; it < NIT; it++) {
        const int s = it & 1;
        cp_wait0();
        __syncthreads();                 // stage s fully staged (x STS + W cp.async)

        if (it + 1 < NIT) {
            const int k0 = (it + 1) * KC;
            xr0 = *(const float4*)&x[(size_t)(tok0 + xt0) * DMODEL + k0 + xc0];
            xr1 = *(const float4*)&x[(size_t)(tok0 + xt1) * DMODEL + k0 + xc1];
            const int d = s ^ 1;
            const uint32_t wdst = sb + OFF_WS + d * KC * SWS * 4;
            cp16(wdst + (wk0 * SWS + we0) * 4, &W[(size_t)(k0 + wk0) * NEXP + we0]);
            cp16(wdst + (wk1 * SWS + we1) * 4, &W[(size_t)(k0 + wk1) * NEXP + we1]);
            cp_commit();
        }

        const float* xs = xsBase + s * KC * SXS;
        const float* ws = wsBase + s * KC * SWS;

        #pragma unroll
        for (int kk = 0; kk < KC; kk++) {
            float2 xa01 = *(const float2*)&xs[kk * SXS + t0];
            float2 xa23 = *(const float2*)&xs[kk * SXS + t0 + 2];
            float4 wv4  = *(const float4*)&ws[kk * SWS + e0];
            const float xv[4] = {xa01.x, xa01.y, xa23.x, xa23.y};
            const float wv[4] = {wv4.x, wv4.y, wv4.z, wv4.w};
            #pragma unroll
            for (int i = 0; i < 4; i++)
                #pragma unroll
                for (int j = 0; j < 4; j++)
                    acc[i][j] = fmaf(xv[i], wv[j], acc[i][j]);
        }

        if (it + 1 < NIT) stage_x(s ^ 1);
    }

    // ---- epilogue: dump logits to smem (stride 68), per-token softmax/top-2 ----
    __syncthreads();
    {
        float* sf = (float*)sAll;
        #pragma unroll
        for (int i = 0; i < 4; i++)
            *(float4*)&sf[(t0 + i) * 68 + e0] =
                make_float4(acc[i][0], acc[i][1], acc[i][2], acc[i][3]);
    }
    __syncthreads();

    if (tid < TPB) {
        const float* sf = (const float*)sAll;
        const float* sbias = (const float*)(sAll + OFF_BIAS);
        float p[64];
        #pragma unroll
        for (int c = 0; c < 64; c++)
            p[c] = sf[tid * 68 + c] + sbias[c];

        float m = p[0];
        #pragma unroll
        for (int c = 1; c < 64; c++) m = fmaxf(m, p[c]);
        float sum = 0.f;
        #pragma unroll
        for (int c = 0; c < 64; c++) { p[c] = __expf(p[c] - m); sum += p[c]; }
        const float inv = 1.f / sum;
        #pragma unroll
        for (int c = 0; c < 64; c++) p[c] *= inv;

        #pragma unroll
        for (int c4 = 0; c4 < 16; c4++)
            *(float4*)&probs_out[(size_t)(tok0 + tid) * NEXP + c4 * 4] =
                make_float4(p[c4 * 4], p[c4 * 4 + 1], p[c4 * 4 + 2], p[c4 * 4 + 3]);

        float p1 = -1.f, p2 = -1.f;
        int e1 = 0, e2 = 0;
        #pragma unroll
        for (int c = 0; c < 64; c++) {
            float pv = p[c];
            if (pv > p1)      { p2 = p1; e2 = e1; p1 = pv; e1 = c; }
            else if (pv > p2) { p2 = pv; e2 = c; }
        }

        const int token = tok0 + tid;
        const float is2 = 1.f / (p1 + p2 + 1e-9f);
        *(float2*)&tkp_out[(size_t)token * 2] = make_float2(p1 * is2, p2 * is2);
        *(float2*)&tki_out[(size_t)token * 2] = make_float2((float)e1, (float)e2);
    }
}

extern "C" void kernel_launch(void* const* d_in, const int* in_sizes, int n_in,
                              void* d_out, int out_size) {
    const float* x = (const float*)d_in[0];   // [4,4096,4096]
    const float* W = (const float*)d_in[1];   // [4096,64]
    const float* b = (const float*)d_in[2];   // [64]

    const int n_tokens = in_sizes[0] / DMODEL;        // 16384
    float* probs = (float*)d_out;
    float* tkp   = probs + (size_t)n_tokens * NEXP;
    float* tki   = tkp + (size_t)n_tokens * 2;

    router_kernel<<<n_tokens / TPB, THREADS>>>(x, W, b, probs, tkp, tki);
}

// round 16
// speedup vs baseline: 2.6934x; 1.1233x over previous
#include <cuda_runtime.h>
#include <cuda_bf16.h>
#include <cstdint>

#define DMODEL  4096
#define NEXP    64
#define TPB     64                  // tokens per CTA
#define KC      32                  // K per tile
#define NIT     (DMODEL / KC)       // 128 tiles
#define THREADS 256

// x tile: token-major [64][36] floats (144B row, 16B-aligned, conflict-free)
// W tile: k-major    [32][72] floats (288B row, 16B-aligned, conflict-free)
#define XROW  36
#define WROW  72
#define XST   (64 * XROW * 4)       // 9216 B per stage
#define WST   (32 * WROW * 4)       // 9216 B per stage
#define OFF_XS 0
#define OFF_WS (2 * XST)            // 18432
#define OFF_BIAS (OFF_WS + 2 * WST) // 36864
#define SM_BYTES (OFF_BIAS + 256)   // 37120

__device__ __forceinline__ uint32_t smem_u32(const void* p) {
    uint32_t a;
    asm("{ .reg .u64 t; cvta.to.shared.u64 t, %1; cvt.u32.u64 %0, t; }" : "=r"(a) : "l"(p));
    return a;
}
__device__ __forceinline__ void cp16(uint32_t dst, const void* src) {
    asm volatile("cp.async.cg.shared.global [%0], [%1], 16;" :: "r"(dst), "l"(src));
}
__device__ __forceinline__ void cp_commit() { asm volatile("cp.async.commit_group;" ::: "memory"); }
__device__ __forceinline__ void cp_wait0()  { asm volatile("cp.async.wait_group 0;" ::: "memory"); }

__global__ __launch_bounds__(THREADS, 2) void router_kernel(
    const float* __restrict__ x, const float* __restrict__ W,
    const float* __restrict__ b,
    float* __restrict__ probs_out, float* __restrict__ tkp_out,
    float* __restrict__ tki_out)
{
    __shared__ __align__(16) char sAll[SM_BYTES];
    const uint32_t sb = smem_u32(sAll);

    const int tid  = threadIdx.x;
    const int tx   = tid & 15;          // 4 experts: e0 = tx*4
    const int ty   = tid >> 4;          // 4 tokens:  t0 = ty*4
    const int e0   = tx * 4;
    const int t0   = ty * 4;
    const int tok0 = blockIdx.x * TPB;

    if (tid < NEXP) *(float*)(sAll + OFF_BIAS + tid * 4) = b[tid];

    // cp.async maps: x tile 512 chunks (row = v>>3, col16 = v&7), W tile 512 (krow = v>>4, c16 = v&15)
    const int xrow0 = tid >> 3,          xcol0 = tid & 7;
    const int xrow1 = (tid + 256) >> 3,  xcol1 = tid & 7;
    const int wrow0 = tid >> 4,          wcol0 = tid & 15;
    const int wrow1 = (tid + 256) >> 4,  wcol1 = tid & 15;

    auto issue_cp = [&](int st, int k0) {
        const uint32_t xd = sb + OFF_XS + st * XST;
        const uint32_t wd = sb + OFF_WS + st * WST;
        cp16(xd + xrow0 * 144 + xcol0 * 16, &x[(size_t)(tok0 + xrow0) * DMODEL + k0 + xcol0 * 4]);
        cp16(xd + xrow1 * 144 + xcol1 * 16, &x[(size_t)(tok0 + xrow1) * DMODEL + k0 + xcol1 * 4]);
        cp16(wd + wrow0 * 288 + wcol0 * 16, &W[(size_t)(k0 + wrow0) * NEXP + wcol0 * 4]);
        cp16(wd + wrow1 * 288 + wcol1 * 16, &W[(size_t)(k0 + wrow1) * NEXP + wcol1 * 4]);
        cp_commit();
    };

    float acc[4][4];
    #pragma unroll
    for (int i = 0; i < 4; i++)
        #pragma unroll
        for (int j = 0; j < 4; j++) acc[i][j] = 0.f;

    // ---- prologue ----
    issue_cp(0, 0);

    // ---- mainloop ----
    #pragma unroll 1
    for (int it = 0; it < NIT; it++) {
        const int s = it & 1;
        cp_wait0();
        __syncthreads();                 // stage s landed; stage s^1 free (prev compute done)

        if (it + 1 < NIT) issue_cp(s ^ 1, (it + 1) * KC);

        const float* xs = (const float*)(sAll + OFF_XS + s * XST);
        const float* ws = (const float*)(sAll + OFF_WS + s * WST);

        #pragma unroll
        for (int kg = 0; kg < KC / 4; kg++) {
            float4 xv[4];
            #pragma unroll
            for (int i = 0; i < 4; i++)
                xv[i] = *(const float4*)&xs[(t0 + i) * XROW + kg * 4];
            #pragma unroll
            for (int kc = 0; kc < 4; kc++) {
                float4 wv = *(const float4*)&ws[(kg * 4 + kc) * WROW + e0];
                const float xk[4] = {
                    kc == 0 ? xv[0].x : kc == 1 ? xv[0].y : kc == 2 ? xv[0].z : xv[0].w,
                    kc == 0 ? xv[1].x : kc == 1 ? xv[1].y : kc == 2 ? xv[1].z : xv[1].w,
                    kc == 0 ? xv[2].x : kc == 1 ? xv[2].y : kc == 2 ? xv[2].z : xv[2].w,
                    kc == 0 ? xv[3].x : kc == 1 ? xv[3].y : kc == 2 ? xv[3].z : xv[3].w };
                #pragma unroll
                for (int i = 0; i < 4; i++) {
                    acc[i][0] = fmaf(xk[i], wv.x, acc[i][0]);
                    acc[i][1] = fmaf(xk[i], wv.y, acc[i][1]);
                    acc[i][2] = fmaf(xk[i], wv.z, acc[i][2]);
                    acc[i][3] = fmaf(xk[i], wv.w, acc[i][3]);
                }
            }
        }
    }

    // ---- epilogue: dump logits to smem (stride 68), per-token softmax/top-2 ----
    __syncthreads();
    {
        float* sf = (float*)sAll;
        #pragma unroll
        for (int i = 0; i < 4; i++)
            *(float4*)&sf[(t0 + i) * 68 + e0] =
                make_float4(acc[i][0], acc[i][1], acc[i][2], acc[i][3]);
    }
    __syncthreads();

    if (tid < TPB) {
        const float* sf = (const float*)sAll;
        const float* sbias = (const float*)(sAll + OFF_BIAS);
        float p[64];
        #pragma unroll
        for (int c = 0; c < 64; c++)
            p[c] = sf[tid * 68 + c] + sbias[c];

        float m = p[0];
        #pragma unroll
        for (int c = 1; c < 64; c++) m = fmaxf(m, p[c]);
        float sum = 0.f;
        #pragma unroll
        for (int c = 0; c < 64; c++) { p[c] = __expf(p[c] - m); sum += p[c]; }
        const float inv = 1.f / sum;
        #pragma unroll
        for (int c = 0; c < 64; c++) p[c] *= inv;

        #pragma unroll
        for (int c4 = 0; c4 < 16; c4++)
            *(float4*)&probs_out[(size_t)(tok0 + tid) * NEXP + c4 * 4] =
                make_float4(p[c4 * 4], p[c4 * 4 + 1], p[c4 * 4 + 2], p[c4 * 4 + 3]);

        float p1 = -1.f, p2 = -1.f;
        int e1 = 0, e2 = 0;
        #pragma unroll
        for (int c = 0; c < 64; c++) {
            float pv = p[c];
            if (pv > p1)      { p2 = p1; e2 = e1; p1 = pv; e1 = c; }
            else if (pv > p2) { p2 = pv; e2 = c; }
        }

        const int token = tok0 + tid;
        const float is2 = 1.f / (p1 + p2 + 1e-9f);
        *(float2*)&tkp_out[(size_t)token * 2] = make_float2(p1 * is2, p2 * is2);
        *(float2*)&tki_out[(size_t)token * 2] = make_float2((float)e1, (float)e2);
    }
}

extern "C" void kernel_launch(void* const* d_in, const int* in_sizes, int n_in,
                              void* d_out, int out_size) {
    const float* x = (const float*)d_in[0];   // [4,4096,4096]
    const float* W = (const float*)d_in[1];   // [4096,64]
    const float* b = (const float*)d_in[2];   // [64]

    const int n_tokens = in_sizes[0] / DMODEL;        // 16384
    float* probs = (float*)d_out;
    float* tkp   = probs + (size_t)n_tokens * NEXP;
    float* tki   = tkp + (size_t)n_tokens * 2;

    router_kernel<<<n_tokens / TPB, THREADS>>>(x, W, b, probs, tkp, tki);
}